// round 7
// baseline (speedup 1.0000x reference)
#include <cuda_runtime.h>
#include <math.h>
#include <stdint.h>

#define FULL 0xffffffffu
typedef unsigned long long u64;
typedef unsigned int u32;

static constexpr int P    = 16;
static constexpr int MAXB = 16384;
static constexpr int NBLK = 296;

// ---------------- scratch (__device__ globals; no allocations) ----------------
__device__ float4 g_Utab0[MAXB * 32];   // bias + u @ W_ih[:, :32]^T (bias folded)
__device__ float4 g_Utab1[MAXB * 32];
__device__ float4 g_Rtab0[32 * 32];     // bias + rel @ W_ih[:, :32]^T (bias folded)
__device__ float4 g_Etab0[32 * 32];     // ent @ W_ih[:, 32:]^T
__device__ float4 g_Rtab1[32 * 32];
__device__ float4 g_Etab1[32 * 32];
__device__ float  g_final0[MAXB * 32];  // per-b summed h (complete)
__device__ float  g_final1[MAXB * 32];
__device__ float  g_lossblk[NBLK];

// ---------------- math helpers ----------------
__device__ __forceinline__ float tanha(float x) {
    float y; asm("tanh.approx.f32 %0,%1;" : "=f"(y) : "f"(x)); return y;
}
__device__ __forceinline__ float sigf(float x) {
    return fmaf(tanha(0.5f * x), 0.5f, 0.5f);
}
__device__ __forceinline__ u32 tf32r(float x) {
    u32 u; asm("cvt.rna.tf32.f32 %0,%1;" : "=r"(u) : "f"(x)); return u;
}
// D = A(16x8 tf32,row) @ B(8x8 tf32,col) + D   (f32 accum)
__device__ __forceinline__ void mma_tf32(float& d0, float& d1, float& d2, float& d3,
                                         u32 a0, u32 a1, u32 a2, u32 a3,
                                         u32 b0, u32 b1) {
    asm("mma.sync.aligned.m16n8k8.row.col.f32.tf32.tf32.f32 "
        "{%0,%1,%2,%3},{%4,%5,%6,%7},{%8,%9},{%0,%1,%2,%3};"
        : "+f"(d0), "+f"(d1), "+f"(d2), "+f"(d3)
        : "r"(a0), "r"(a1), "r"(a2), "r"(a3), "r"(b0), "r"(b1));
}

// ---------------- precompute E/R contribution tables (tiny) ----------------
__global__ void precompute_tables_kernel(const float* __restrict__ rel_table,
                                         const float* __restrict__ ent_table,
                                         const float* __restrict__ wih0,
                                         const float* __restrict__ wih1,
                                         const float* __restrict__ bih0,
                                         const float* __restrict__ bhh0,
                                         const float* __restrict__ bih1,
                                         const float* __restrict__ bhh1) {
    int tid   = threadIdx.x;          // 1024
    int which = blockIdx.x;           // 0:Rtab0 1:Etab0 2:Rtab1 3:Etab1
    int r     = tid >> 5;
    int lane  = tid & 31;
    const float* w   = (which < 2) ? wih0 : wih1;
    const float* src = (which & 1) ? ent_table : rel_table;
    int colofs       = (which & 1) ? 32 : 0;

    float4 acc = make_float4(0.f, 0.f, 0.f, 0.f);
    if (!(which & 1)) {  // Rtab: fold bias in
        const float* bi = (which < 2) ? bih0 : bih1;
        const float* bh = (which < 2) ? bhh0 : bhh1;
        acc.x = bi[lane]      + bh[lane];
        acc.y = bi[32 + lane] + bh[32 + lane];
        acc.z = bi[64 + lane] + bh[64 + lane];
        acc.w = bi[96 + lane] + bh[96 + lane];
    }
    #pragma unroll
    for (int k = 0; k < 32; k++) {
        float x = src[r * 32 + k];
        acc.x += x * w[(0 * 32 + lane) * 64 + colofs + k];
        acc.y += x * w[(1 * 32 + lane) * 64 + colofs + k];
        acc.z += x * w[(2 * 32 + lane) * 64 + colofs + k];
        acc.w += x * w[(3 * 32 + lane) * 64 + colofs + k];
    }
    float4* dst = (which == 0) ? g_Rtab0 : (which == 1) ? g_Etab0
                : (which == 2) ? g_Rtab1 : g_Etab1;
    dst[tid] = acc;
}

// ---------------- precompute per-b user contribution (bias folded) ----------------
__global__ __launch_bounds__(256) void precompute_u_kernel(
        const float* __restrict__ user_table,
        const float* __restrict__ wih0,
        const float* __restrict__ wih1,
        const float* __restrict__ bih0,
        const float* __restrict__ bhh0,
        const float* __restrict__ bih1,
        const float* __restrict__ bhh1,
        const int* __restrict__ users, int B) {
    __shared__ float4 w0[32 * 32];
    __shared__ float4 w1[32 * 32];
    int tid = threadIdx.x;
    for (int i = tid; i < 32 * 32; i += 256) {
        int k = i >> 5, l = i & 31;
        w0[i] = make_float4(wih0[l * 64 + k], wih0[(l + 32) * 64 + k],
                            wih0[(l + 64) * 64 + k], wih0[(l + 96) * 64 + k]);
        w1[i] = make_float4(wih1[l * 64 + k], wih1[(l + 32) * 64 + k],
                            wih1[(l + 64) * 64 + k], wih1[(l + 96) * 64 + k]);
    }
    __syncthreads();

    int wid = tid >> 5, lane = tid & 31;
    float4 bias0 = make_float4(bih0[lane]      + bhh0[lane],
                               bih0[32 + lane] + bhh0[32 + lane],
                               bih0[64 + lane] + bhh0[64 + lane],
                               bih0[96 + lane] + bhh0[96 + lane]);
    float4 bias1 = make_float4(bih1[lane]      + bhh1[lane],
                               bih1[32 + lane] + bhh1[32 + lane],
                               bih1[64 + lane] + bhh1[64 + lane],
                               bih1[96 + lane] + bhh1[96 + lane]);

    int gw = blockIdx.x * 8 + wid, TW = gridDim.x * 8;
    for (int b = gw; b < B; b += TW) {
        float u = user_table[users[b] * 32 + lane];
        float4 a0 = bias0, a1 = bias1;
        #pragma unroll
        for (int k = 0; k < 32; k++) {
            float uk = __shfl_sync(FULL, u, k);
            float4 q0 = w0[k * 32 + lane];
            float4 q1 = w1[k * 32 + lane];
            a0.x += uk * q0.x; a0.y += uk * q0.y; a0.z += uk * q0.z; a0.w += uk * q0.w;
            a1.x += uk * q1.x; a1.y += uk * q1.y; a1.z += uk * q1.z; a1.w += uk * q1.w;
        }
        g_Utab0[b * 32 + lane] = a0;
        g_Utab1[b * 32 + lane] = a1;
    }
}

// ---------------- mma.sync hop kernel ----------------
// Warp = one batch row b (16 paths = M-tile). Recurrent step: m16n8k8 tf32 MMA
// with augmented K=96: gates = [H | onehot(ri) | onehot(ti)] @ [Whh^T; Rtab'; Etab].
// Activations in D-fragment layout; h recirculated to A layout via shuffles.
template <int NSTEP, int STRIDE, int HOP>
__global__ __launch_bounds__(256, 2) void hop_mma_kernel(
        const float* __restrict__ whh,
        const int* __restrict__ items,
        const int* __restrict__ lp, int B) {
    // Fragment-ordered B: Bs[(kt*16+nt)*32 + lane] = {B[8kt+t][8nt+gq], B[8kt+t+4][8nt+gq]}
    // where t=lane&3, gq=lane>>2.   12 kt x 16 nt x 32 lanes x 8B = 48KB exactly.
    __shared__ uint2 Bs[12 * 16 * 32];

    const float* Rtabf = (const float*)(HOP ? g_Rtab1 : g_Rtab0);
    const float* Etabf = (const float*)(HOP ? g_Etab1 : g_Etab0);
    const float4* Etab4 = HOP ? g_Etab1 : g_Etab0;
    const float4* Utab4 = HOP ? g_Utab1 : g_Utab0;
    float* gout = HOP ? g_final1 : g_final0;

    int tid = threadIdx.x;
    // ---- fill Bs (once per CTA): rows 0-31 Whh^T, 32-63 Rtab', 64-95 Etab ----
    for (int i = tid; i < 12 * 16 * 32; i += 256) {
        int kt = i >> 9;
        int nt = (i >> 5) & 15;
        int ln = i & 31;
        int t = ln & 3, gq = ln >> 2;
        int g = 8 * nt + gq;
        float x, y;
        if (kt < 4) {
            x = whh[g * 32 + 8 * kt + t];
            y = whh[g * 32 + 8 * kt + t + 4];
        } else {
            const float* tabf = (kt < 8) ? Rtabf : Etabf;
            int idx0 = 8 * ((kt < 8) ? (kt - 4) : (kt - 8)) + t;
            int j  = 8 * (nt & 3) + gq;
            int gt = nt >> 2;
            x = tabf[(idx0 * 32 + j) * 4 + gt];
            y = tabf[((idx0 + 4) * 32 + j) * 4 + gt];
        }
        Bs[i] = make_uint2(tf32r(x), tf32r(y));
    }
    __syncthreads();

    int wid = tid >> 5, lane = tid & 31;
    int r0 = lane >> 2, t = lane & 3;
    int srcA = (r0 << 2) | (t >> 1);
    int srcB = srcA + 2;

    int gw = blockIdx.x * 8 + wid;
    int TW = NBLK * 8;

    for (int b = gw; b < B; b += TW) {
        int item = __ldg(&items[b]);
        // lanes 0..15 own path lane; pack 5-bit indices
        int p = lane & 15;
        const int* lpb = lp + (size_t)item * (P * STRIDE) + p * STRIDE;
        u32 ip = 0;
        #pragma unroll
        for (int j = 0; j < STRIDE; j++)
            ip |= ((u32)__ldg(&lpb[j])) << (5 * j);
        u32 idxA = __shfl_sync(FULL, ip, r0);       // path r0
        u32 idxB = __shfl_sync(FULL, ip, r0 + 8);   // path r0+8

        // ---- step 0 in D-fragment layout: gates = U'(bias) + E[seed] ----
        float c_st[16], h_d[16];   // flat = jt*4 + pp*2 + cc
        {
            const float4* Ut = Utab4 + (size_t)b * 32;
            const float4* EA = Etab4 + (idxA & 31) * 32;
            const float4* EB = Etab4 + (idxB & 31) * 32;
            #pragma unroll
            for (int jt = 0; jt < 4; jt++) {
                #pragma unroll
                for (int cc = 0; cc < 2; cc++) {
                    int j = 8 * jt + 2 * t + cc;
                    float4 u4 = Ut[j];
                    float4 e = EA[j];
                    float c0 = sigf(u4.x + e.x) * tanha(u4.z + e.z);
                    c_st[jt * 4 + cc] = c0;
                    h_d[jt * 4 + cc]  = sigf(u4.w + e.w) * tanha(c0);
                    e = EB[j];
                    c0 = sigf(u4.x + e.x) * tanha(u4.z + e.z);
                    c_st[jt * 4 + 2 + cc] = c0;
                    h_d[jt * 4 + 2 + cc]  = sigf(u4.w + e.w) * tanha(c0);
                }
            }
        }

        // ---- recurrent steps ----
        #pragma unroll
        for (int s = 1; s < NSTEP; s++) {
            u32 aa[48];
            // h part (kt 0..3): relayout D-frag -> A-frag via shuffles
            #pragma unroll
            for (int kt = 0; kt < 4; kt++) {
                float y0, y1;
                y0 = __shfl_sync(FULL, h_d[kt * 4 + 0], srcA);
                y1 = __shfl_sync(FULL, h_d[kt * 4 + 1], srcA);
                aa[kt * 4 + 0] = tf32r((t & 1) ? y1 : y0);
                y0 = __shfl_sync(FULL, h_d[kt * 4 + 2], srcA);
                y1 = __shfl_sync(FULL, h_d[kt * 4 + 3], srcA);
                aa[kt * 4 + 1] = tf32r((t & 1) ? y1 : y0);
                y0 = __shfl_sync(FULL, h_d[kt * 4 + 0], srcB);
                y1 = __shfl_sync(FULL, h_d[kt * 4 + 1], srcB);
                aa[kt * 4 + 2] = tf32r((t & 1) ? y1 : y0);
                y0 = __shfl_sync(FULL, h_d[kt * 4 + 2], srcB);
                y1 = __shfl_sync(FULL, h_d[kt * 4 + 3], srcB);
                aa[kt * 4 + 3] = tf32r((t & 1) ? y1 : y0);
            }
            // one-hot parts (kt 4..11): pure ALU, zero loads
            u32 ri0 = (idxA >> (5 * (2 * s - 1))) & 31;
            u32 ri1 = (idxB >> (5 * (2 * s - 1))) & 31;
            u32 ti0 = (idxA >> (5 * (2 * s))) & 31;
            u32 ti1 = (idxB >> (5 * (2 * s))) & 31;
            #pragma unroll
            for (int kt = 0; kt < 4; kt++) {
                u32 kb = 8 * kt + t;
                aa[16 + kt * 4 + 0] = (ri0 == kb)     ? 0x3F800000u : 0u;
                aa[16 + kt * 4 + 1] = (ri1 == kb)     ? 0x3F800000u : 0u;
                aa[16 + kt * 4 + 2] = (ri0 == kb + 4) ? 0x3F800000u : 0u;
                aa[16 + kt * 4 + 3] = (ri1 == kb + 4) ? 0x3F800000u : 0u;
                aa[32 + kt * 4 + 0] = (ti0 == kb)     ? 0x3F800000u : 0u;
                aa[32 + kt * 4 + 1] = (ti1 == kb)     ? 0x3F800000u : 0u;
                aa[32 + kt * 4 + 2] = (ti0 == kb + 4) ? 0x3F800000u : 0u;
                aa[32 + kt * 4 + 3] = (ti1 == kb + 4) ? 0x3F800000u : 0u;
            }

            // MMA + activation per j-tile (tiles jt, jt+4, jt+8, jt+12 = gates i,f,g,o)
            #pragma unroll
            for (int jt = 0; jt < 4; jt++) {
                float G[4][4];
                #pragma unroll
                for (int gt = 0; gt < 4; gt++) {
                    int nt = jt + 4 * gt;
                    float d0 = 0.f, d1 = 0.f, d2 = 0.f, d3 = 0.f;
                    #pragma unroll
                    for (int kt = 0; kt < 12; kt++) {
                        uint2 bb = Bs[(kt * 16 + nt) * 32 + lane];
                        mma_tf32(d0, d1, d2, d3,
                                 aa[kt * 4], aa[kt * 4 + 1], aa[kt * 4 + 2], aa[kt * 4 + 3],
                                 bb.x, bb.y);
                    }
                    G[gt][0] = d0; G[gt][1] = d1; G[gt][2] = d2; G[gt][3] = d3;
                }
                #pragma unroll
                for (int dq = 0; dq < 4; dq++) {
                    int ci = jt * 4 + dq;   // dq = pp*2 + cc matches d-frag rows/cols
                    float c = sigf(G[1][dq]) * c_st[ci] + sigf(G[0][dq]) * tanha(G[2][dq]);
                    c_st[ci] = c;
                    h_d[ci] = sigf(G[3][dq]) * tanha(c);
                }
            }
        }

        // ---- reduce 16 paths -> per-b sum, write ----
        #pragma unroll
        for (int jt = 0; jt < 4; jt++) {
            #pragma unroll
            for (int cc = 0; cc < 2; cc++) {
                float v = h_d[jt * 4 + cc] + h_d[jt * 4 + 2 + cc];
                v += __shfl_xor_sync(FULL, v, 4);
                v += __shfl_xor_sync(FULL, v, 8);
                v += __shfl_xor_sync(FULL, v, 16);
                if (lane < 4)
                    gout[b * 32 + 8 * jt + 2 * lane + cc] = v;
            }
        }
    }
}

// ---------------- combine: agg matmuls, scores, sigmoid, block loss partials ----------------
__global__ __launch_bounds__(256) void combine_kernel(
        const float* __restrict__ user_table,
        const float* __restrict__ ent_table,
        const float* __restrict__ agg_w,
        const float* __restrict__ agg_b,
        const int* __restrict__ users,
        const int* __restrict__ items,
        const int* __restrict__ ratings,
        float* __restrict__ out, int B) {
    __shared__ float aggT[32 * 32];
    __shared__ float aggb_sm[32];
    __shared__ float lred[8];
    int tid = threadIdx.x;
    for (int i = tid; i < 32 * 32; i += 256) {
        int k = i >> 5, j = i & 31;
        aggT[i] = agg_w[j * 32 + k];
    }
    if (tid < 32) aggb_sm[tid] = agg_b[tid];
    __syncthreads();

    int wid = tid >> 5, lane = tid & 31;
    int gw = blockIdx.x * 8 + wid, TW = gridDim.x * 8;
    float loss_acc = 0.f;

    for (int b = gw; b < B; b += TW) {
        int item = items[b];
        int user = users[b];

        float f0 = g_final0[b * 32 + lane];
        float f1 = g_final1[b * 32 + lane];

        float v = ent_table[item * 32 + lane] + f0;
        float acc = aggb_sm[lane];
        #pragma unroll
        for (int k = 0; k < 32; k++)
            acc += __shfl_sync(FULL, v, k) * aggT[k * 32 + lane];

        v = acc + f1;
        acc = aggb_sm[lane];
        #pragma unroll
        for (int k = 0; k < 32; k++)
            acc += __shfl_sync(FULL, v, k) * aggT[k * 32 + lane];

        float prod = user_table[user * 32 + lane] * acc;
        #pragma unroll
        for (int o = 16; o; o >>= 1) prod += __shfl_xor_sync(FULL, prod, o);

        if (lane == 0) {
            float s = prod;
            out[1 + b]     = 1.0f / (1.0f + __expf(-s));
            out[1 + B + b] = (float)item;
            float r    = (float)ratings[b];
            float ls_p = fminf(s, 0.0f)  - log1pf(__expf(-fabsf(s)));
            float ls_n = fminf(-s, 0.0f) - log1pf(__expf(-fabsf(s)));
            loss_acc += -(r * ls_p + (1.0f - r) * ls_n);
        }
    }

    if (lane == 0) lred[wid] = loss_acc;
    __syncthreads();
    if (tid == 0) {
        float s = 0.f;
        #pragma unroll
        for (int w = 0; w < 8; w++) s += lred[w];
        g_lossblk[blockIdx.x] = s;
    }
}

// ---------------- final loss reduction ----------------
__global__ void loss_kernel(float* __restrict__ out, int B, int nblk) {
    __shared__ float sm[512];
    int tid = threadIdx.x;
    float s = 0.f;
    for (int i = tid; i < nblk; i += 512) s += g_lossblk[i];
    sm[tid] = s;
    __syncthreads();
    for (int o = 256; o; o >>= 1) {
        if (tid < o) sm[tid] += sm[tid + o];
        __syncthreads();
    }
    if (tid == 0) out[0] = sm[0] / (float)B;
}

// ---------------- launch ----------------
extern "C" void kernel_launch(void* const* d_in, const int* in_sizes, int n_in,
                              void* d_out, int out_size) {
    const float* user_table = (const float*)d_in[0];
    const float* ent_table  = (const float*)d_in[1];
    const float* rel_table  = (const float*)d_in[2];
    const float* w_ih0      = (const float*)d_in[3];
    const float* w_hh0      = (const float*)d_in[4];
    const float* b_ih0      = (const float*)d_in[5];
    const float* b_hh0      = (const float*)d_in[6];
    const float* w_ih1      = (const float*)d_in[7];
    const float* w_hh1      = (const float*)d_in[8];
    const float* b_ih1      = (const float*)d_in[9];
    const float* b_hh1      = (const float*)d_in[10];
    const float* agg_w      = (const float*)d_in[11];
    const float* agg_b      = (const float*)d_in[12];
    const int*   users      = (const int*)d_in[13];
    const int*   items      = (const int*)d_in[14];
    const int*   ratings    = (const int*)d_in[15];
    const int*   lp0        = (const int*)d_in[16];
    const int*   lp1        = (const int*)d_in[17];
    float*       out        = (float*)d_out;

    int B = in_sizes[13];

    precompute_tables_kernel<<<4, 1024>>>(rel_table, ent_table, w_ih0, w_ih1,
                                          b_ih0, b_hh0, b_ih1, b_hh1);
    precompute_u_kernel<<<NBLK, 256>>>(user_table, w_ih0, w_ih1,
                                       b_ih0, b_hh0, b_ih1, b_hh1, users, B);
    hop_mma_kernel<2, 3, 0><<<NBLK, 256>>>(w_hh0, items, lp0, B);
    hop_mma_kernel<3, 5, 1><<<NBLK, 256>>>(w_hh1, items, lp1, B);
    combine_kernel<<<NBLK, 256>>>(user_table, ent_table, agg_w, agg_b,
                                  users, items, ratings, out, B);
    loss_kernel<<<1, 512>>>(out, B, NBLK);
}

// round 8
// speedup vs baseline: 1.3564x; 1.3564x over previous
#include <cuda_runtime.h>
#include <math.h>
#include <stdint.h>

#define FULL 0xffffffffu
typedef unsigned long long u64;
typedef unsigned int u32;

static constexpr int P    = 16;
static constexpr int MAXB = 16384;
static constexpr int NBLK = 296;

// ---------------- scratch (__device__ globals; no allocations) ----------------
__device__ float4 g_Utab0[MAXB * 32];   // bias + u @ W_ih[:, :32]^T (bias folded)
__device__ float4 g_Utab1[MAXB * 32];
__device__ float4 g_Rtab0[32 * 32];     // bias + rel @ W_ih[:, :32]^T (bias folded)
__device__ float4 g_Etab0[32 * 32];     // ent @ W_ih[:, 32:]^T
__device__ float4 g_Rtab1[32 * 32];
__device__ float4 g_Etab1[32 * 32];
__device__ float  g_final0[MAXB * 32];  // per-b summed h (complete)
__device__ float  g_final1[MAXB * 32];
__device__ float  g_lossblk[NBLK];

// ---------------- math helpers ----------------
__device__ __forceinline__ float tanha(float x) {
    float y; asm("tanh.approx.f32 %0,%1;" : "=f"(y) : "f"(x)); return y;
}
__device__ __forceinline__ float sigf(float x) {
    return fmaf(tanha(0.5f * x), 0.5f, 0.5f);
}
__device__ __forceinline__ u32 tf32r(float x) {
    u32 u; asm("cvt.rna.tf32.f32 %0,%1;" : "=r"(u) : "f"(x)); return u;
}
// D = A(16x8 tf32,row) @ B(8x8 tf32,col) + D   (f32 accum)
__device__ __forceinline__ void mma_tf32(float& d0, float& d1, float& d2, float& d3,
                                         u32 a0, u32 a1, u32 a2, u32 a3,
                                         u32 b0, u32 b1) {
    asm("mma.sync.aligned.m16n8k8.row.col.f32.tf32.tf32.f32 "
        "{%0,%1,%2,%3},{%4,%5,%6,%7},{%8,%9},{%0,%1,%2,%3};"
        : "+f"(d0), "+f"(d1), "+f"(d2), "+f"(d3)
        : "r"(a0), "r"(a1), "r"(a2), "r"(a3), "r"(b0), "r"(b1));
}

// ---------------- precompute E/R contribution tables (tiny) ----------------
__global__ void precompute_tables_kernel(const float* __restrict__ rel_table,
                                         const float* __restrict__ ent_table,
                                         const float* __restrict__ wih0,
                                         const float* __restrict__ wih1,
                                         const float* __restrict__ bih0,
                                         const float* __restrict__ bhh0,
                                         const float* __restrict__ bih1,
                                         const float* __restrict__ bhh1) {
    int tid   = threadIdx.x;          // 1024
    int which = blockIdx.x;           // 0:Rtab0 1:Etab0 2:Rtab1 3:Etab1
    int r     = tid >> 5;
    int lane  = tid & 31;
    const float* w   = (which < 2) ? wih0 : wih1;
    const float* src = (which & 1) ? ent_table : rel_table;
    int colofs       = (which & 1) ? 32 : 0;

    float4 acc = make_float4(0.f, 0.f, 0.f, 0.f);
    if (!(which & 1)) {  // Rtab: fold bias in
        const float* bi = (which < 2) ? bih0 : bih1;
        const float* bh = (which < 2) ? bhh0 : bhh1;
        acc.x = bi[lane]      + bh[lane];
        acc.y = bi[32 + lane] + bh[32 + lane];
        acc.z = bi[64 + lane] + bh[64 + lane];
        acc.w = bi[96 + lane] + bh[96 + lane];
    }
    #pragma unroll
    for (int k = 0; k < 32; k++) {
        float x = src[r * 32 + k];
        acc.x += x * w[(0 * 32 + lane) * 64 + colofs + k];
        acc.y += x * w[(1 * 32 + lane) * 64 + colofs + k];
        acc.z += x * w[(2 * 32 + lane) * 64 + colofs + k];
        acc.w += x * w[(3 * 32 + lane) * 64 + colofs + k];
    }
    float4* dst = (which == 0) ? g_Rtab0 : (which == 1) ? g_Etab0
                : (which == 2) ? g_Rtab1 : g_Etab1;
    dst[tid] = acc;
}

// ---------------- precompute per-b user contribution (bias folded) ----------------
__global__ __launch_bounds__(256) void precompute_u_kernel(
        const float* __restrict__ user_table,
        const float* __restrict__ wih0,
        const float* __restrict__ wih1,
        const float* __restrict__ bih0,
        const float* __restrict__ bhh0,
        const float* __restrict__ bih1,
        const float* __restrict__ bhh1,
        const int* __restrict__ users, int B) {
    __shared__ float4 w0[32 * 32];
    __shared__ float4 w1[32 * 32];
    int tid = threadIdx.x;
    for (int i = tid; i < 32 * 32; i += 256) {
        int k = i >> 5, l = i & 31;
        w0[i] = make_float4(wih0[l * 64 + k], wih0[(l + 32) * 64 + k],
                            wih0[(l + 64) * 64 + k], wih0[(l + 96) * 64 + k]);
        w1[i] = make_float4(wih1[l * 64 + k], wih1[(l + 32) * 64 + k],
                            wih1[(l + 64) * 64 + k], wih1[(l + 96) * 64 + k]);
    }
    __syncthreads();

    int wid = tid >> 5, lane = tid & 31;
    float4 bias0 = make_float4(bih0[lane]      + bhh0[lane],
                               bih0[32 + lane] + bhh0[32 + lane],
                               bih0[64 + lane] + bhh0[64 + lane],
                               bih0[96 + lane] + bhh0[96 + lane]);
    float4 bias1 = make_float4(bih1[lane]      + bhh1[lane],
                               bih1[32 + lane] + bhh1[32 + lane],
                               bih1[64 + lane] + bhh1[64 + lane],
                               bih1[96 + lane] + bhh1[96 + lane]);

    int gw = blockIdx.x * 8 + wid, TW = gridDim.x * 8;
    for (int b = gw; b < B; b += TW) {
        float u = user_table[users[b] * 32 + lane];
        float4 a0 = bias0, a1 = bias1;
        #pragma unroll
        for (int k = 0; k < 32; k++) {
            float uk = __shfl_sync(FULL, u, k);
            float4 q0 = w0[k * 32 + lane];
            float4 q1 = w1[k * 32 + lane];
            a0.x += uk * q0.x; a0.y += uk * q0.y; a0.z += uk * q0.z; a0.w += uk * q0.w;
            a1.x += uk * q1.x; a1.y += uk * q1.y; a1.z += uk * q1.z; a1.w += uk * q1.w;
        }
        g_Utab0[b * 32 + lane] = a0;
        g_Utab1[b * 32 + lane] = a1;
    }
}

// ---------------- mma.sync hop kernel (K=32 only, tables added in D-layout) ----------------
// Warp = one batch row b (16 paths = M-tile). Recurrent step:
//   gates = H[16x32] @ Whh^T[32x128] (tensor core) + Rtab'[ri] + Etab[ti] (L1 float4 gathers)
template <int NSTEP, int STRIDE, int HOP>
__global__ __launch_bounds__(256, 2) void hop_mma_kernel(
        const float* __restrict__ whh,
        const int* __restrict__ items,
        const int* __restrict__ lp, int B) {
    // Fragment-ordered B (Whh only): Bs[(kt*16+nt)*32 + lane] =
    //   {Whh^T[8kt+t][8nt+gq], Whh^T[8kt+t+4][8nt+gq]},  t=lane&3, gq=lane>>2.  16KB.
    __shared__ uint2 Bs[4 * 16 * 32];

    const float4* Rtab4 = HOP ? g_Rtab1 : g_Rtab0;
    const float4* Etab4 = HOP ? g_Etab1 : g_Etab0;
    const float4* Utab4 = HOP ? g_Utab1 : g_Utab0;
    float* gout = HOP ? g_final1 : g_final0;

    int tid = threadIdx.x;
    // ---- fill Bs (once per CTA) ----
    for (int i = tid; i < 4 * 16 * 32; i += 256) {
        int kt = i >> 9;
        int nt = (i >> 5) & 15;
        int ln = i & 31;
        int t = ln & 3, gq = ln >> 2;
        int g = 8 * nt + gq;
        Bs[i] = make_uint2(tf32r(whh[g * 32 + 8 * kt + t]),
                           tf32r(whh[g * 32 + 8 * kt + t + 4]));
    }
    __syncthreads();

    int wid = tid >> 5, lane = tid & 31;
    int r0 = lane >> 2, t = lane & 3;
    int srcA = (r0 << 2) | (t >> 1);
    int srcB = srcA + 2;

    int gw = blockIdx.x * 8 + wid;
    int TW = NBLK * 8;

    for (int b = gw; b < B; b += TW) {
        int item = __ldg(&items[b]);
        // lanes 0..15 own path lane; pack 5-bit indices
        int p = lane & 15;
        const int* lpb = lp + (size_t)item * (P * STRIDE) + p * STRIDE;
        u32 ip = 0;
        #pragma unroll
        for (int j = 0; j < STRIDE; j++)
            ip |= ((u32)__ldg(&lpb[j])) << (5 * j);
        u32 idxA = __shfl_sync(FULL, ip, r0);       // path r0
        u32 idxB = __shfl_sync(FULL, ip, r0 + 8);   // path r0+8

        // ---- step 0 in D-fragment layout: gates = U'(bias) + E[seed] ----
        float c_st[16], h_d[16];   // flat = jt*4 + (path?2:0) + cc
        {
            const float4* Ut = Utab4 + (size_t)b * 32;
            const float4* EA = Etab4 + (idxA & 31) * 32;
            const float4* EB = Etab4 + (idxB & 31) * 32;
            #pragma unroll
            for (int jt = 0; jt < 4; jt++) {
                #pragma unroll
                for (int cc = 0; cc < 2; cc++) {
                    int j = 8 * jt + 2 * t + cc;
                    float4 u4 = Ut[j];
                    float4 e = EA[j];
                    float c0 = sigf(u4.x + e.x) * tanha(u4.z + e.z);
                    c_st[jt * 4 + cc] = c0;
                    h_d[jt * 4 + cc]  = sigf(u4.w + e.w) * tanha(c0);
                    e = EB[j];
                    c0 = sigf(u4.x + e.x) * tanha(u4.z + e.z);
                    c_st[jt * 4 + 2 + cc] = c0;
                    h_d[jt * 4 + 2 + cc]  = sigf(u4.w + e.w) * tanha(c0);
                }
            }
        }

        // ---- recurrent steps ----
        #pragma unroll
        for (int s = 1; s < NSTEP; s++) {
            // relayout h: D-frag -> A-frag via shuffles (kt 0..3)
            u32 aa[16];
            #pragma unroll
            for (int kt = 0; kt < 4; kt++) {
                float y0, y1;
                y0 = __shfl_sync(FULL, h_d[kt * 4 + 0], srcA);
                y1 = __shfl_sync(FULL, h_d[kt * 4 + 1], srcA);
                aa[kt * 4 + 0] = tf32r((t & 1) ? y1 : y0);
                y0 = __shfl_sync(FULL, h_d[kt * 4 + 2], srcA);
                y1 = __shfl_sync(FULL, h_d[kt * 4 + 3], srcA);
                aa[kt * 4 + 1] = tf32r((t & 1) ? y1 : y0);
                y0 = __shfl_sync(FULL, h_d[kt * 4 + 0], srcB);
                y1 = __shfl_sync(FULL, h_d[kt * 4 + 1], srcB);
                aa[kt * 4 + 2] = tf32r((t & 1) ? y1 : y0);
                y0 = __shfl_sync(FULL, h_d[kt * 4 + 2], srcB);
                y1 = __shfl_sync(FULL, h_d[kt * 4 + 3], srcB);
                aa[kt * 4 + 3] = tf32r((t & 1) ? y1 : y0);
            }

            u32 riA = (idxA >> (5 * (2 * s - 1))) & 31;
            u32 riB = (idxB >> (5 * (2 * s - 1))) & 31;
            u32 tiA = (idxA >> (5 * (2 * s))) & 31;
            u32 tiB = (idxB >> (5 * (2 * s))) & 31;
            const float4* RA = Rtab4 + riA * 32;
            const float4* RB = Rtab4 + riB * 32;
            const float4* TA = Etab4 + tiA * 32;
            const float4* TB = Etab4 + tiB * 32;

            // MMA (kt 0..3) + table adds + activation per j-tile
            #pragma unroll
            for (int jt = 0; jt < 4; jt++) {
                float G[4][4];   // [gate i/f/g/o][pp*2+cc]
                #pragma unroll
                for (int gt = 0; gt < 4; gt++) {
                    int nt = jt + 4 * gt;
                    float d0 = 0.f, d1 = 0.f, d2 = 0.f, d3 = 0.f;
                    #pragma unroll
                    for (int kt = 0; kt < 4; kt++) {
                        uint2 bb = Bs[(kt * 16 + nt) * 32 + lane];
                        mma_tf32(d0, d1, d2, d3,
                                 aa[kt * 4], aa[kt * 4 + 1], aa[kt * 4 + 2], aa[kt * 4 + 3],
                                 bb.x, bb.y);
                    }
                    G[gt][0] = d0; G[gt][1] = d1; G[gt][2] = d2; G[gt][3] = d3;
                }
                // add Rtab' (bias folded) + Etab contributions (L1-resident float4s)
                #pragma unroll
                for (int cc = 0; cc < 2; cc++) {
                    int j = 8 * jt + 2 * t + cc;
                    float4 ra = RA[j], ea = TA[j];
                    G[0][cc] += ra.x + ea.x;
                    G[1][cc] += ra.y + ea.y;
                    G[2][cc] += ra.z + ea.z;
                    G[3][cc] += ra.w + ea.w;
                    float4 rb = RB[j], eb = TB[j];
                    G[0][2 + cc] += rb.x + eb.x;
                    G[1][2 + cc] += rb.y + eb.y;
                    G[2][2 + cc] += rb.z + eb.z;
                    G[3][2 + cc] += rb.w + eb.w;
                }
                #pragma unroll
                for (int dq = 0; dq < 4; dq++) {
                    int ci = jt * 4 + dq;
                    float c = sigf(G[1][dq]) * c_st[ci] + sigf(G[0][dq]) * tanha(G[2][dq]);
                    c_st[ci] = c;
                    h_d[ci] = sigf(G[3][dq]) * tanha(c);
                }
            }
        }

        // ---- reduce 16 paths -> per-b sum, write ----
        #pragma unroll
        for (int jt = 0; jt < 4; jt++) {
            #pragma unroll
            for (int cc = 0; cc < 2; cc++) {
                float v = h_d[jt * 4 + cc] + h_d[jt * 4 + 2 + cc];
                v += __shfl_xor_sync(FULL, v, 4);
                v += __shfl_xor_sync(FULL, v, 8);
                v += __shfl_xor_sync(FULL, v, 16);
                if (lane < 4)
                    gout[b * 32 + 8 * jt + 2 * lane + cc] = v;
            }
        }
    }
}

// ---------------- combine: agg matmuls, scores, sigmoid, block loss partials ----------------
__global__ __launch_bounds__(256) void combine_kernel(
        const float* __restrict__ user_table,
        const float* __restrict__ ent_table,
        const float* __restrict__ agg_w,
        const float* __restrict__ agg_b,
        const int* __restrict__ users,
        const int* __restrict__ items,
        const int* __restrict__ ratings,
        float* __restrict__ out, int B) {
    __shared__ float aggT[32 * 32];
    __shared__ float aggb_sm[32];
    __shared__ float lred[8];
    int tid = threadIdx.x;
    for (int i = tid; i < 32 * 32; i += 256) {
        int k = i >> 5, j = i & 31;
        aggT[i] = agg_w[j * 32 + k];
    }
    if (tid < 32) aggb_sm[tid] = agg_b[tid];
    __syncthreads();

    int wid = tid >> 5, lane = tid & 31;
    int gw = blockIdx.x * 8 + wid, TW = gridDim.x * 8;
    float loss_acc = 0.f;

    for (int b = gw; b < B; b += TW) {
        int item = items[b];
        int user = users[b];

        float f0 = g_final0[b * 32 + lane];
        float f1 = g_final1[b * 32 + lane];

        float v = ent_table[item * 32 + lane] + f0;
        float acc = aggb_sm[lane];
        #pragma unroll
        for (int k = 0; k < 32; k++)
            acc += __shfl_sync(FULL, v, k) * aggT[k * 32 + lane];

        v = acc + f1;
        acc = aggb_sm[lane];
        #pragma unroll
        for (int k = 0; k < 32; k++)
            acc += __shfl_sync(FULL, v, k) * aggT[k * 32 + lane];

        float prod = user_table[user * 32 + lane] * acc;
        #pragma unroll
        for (int o = 16; o; o >>= 1) prod += __shfl_xor_sync(FULL, prod, o);

        if (lane == 0) {
            float s = prod;
            out[1 + b]     = 1.0f / (1.0f + __expf(-s));
            out[1 + B + b] = (float)item;
            float r    = (float)ratings[b];
            float ls_p = fminf(s, 0.0f)  - log1pf(__expf(-fabsf(s)));
            float ls_n = fminf(-s, 0.0f) - log1pf(__expf(-fabsf(s)));
            loss_acc += -(r * ls_p + (1.0f - r) * ls_n);
        }
    }

    if (lane == 0) lred[wid] = loss_acc;
    __syncthreads();
    if (tid == 0) {
        float s = 0.f;
        #pragma unroll
        for (int w = 0; w < 8; w++) s += lred[w];
        g_lossblk[blockIdx.x] = s;
    }
}

// ---------------- final loss reduction ----------------
__global__ void loss_kernel(float* __restrict__ out, int B, int nblk) {
    __shared__ float sm[512];
    int tid = threadIdx.x;
    float s = 0.f;
    for (int i = tid; i < nblk; i += 512) s += g_lossblk[i];
    sm[tid] = s;
    __syncthreads();
    for (int o = 256; o; o >>= 1) {
        if (tid < o) sm[tid] += sm[tid + o];
        __syncthreads();
    }
    if (tid == 0) out[0] = sm[0] / (float)B;
}

// ---------------- launch ----------------
extern "C" void kernel_launch(void* const* d_in, const int* in_sizes, int n_in,
                              void* d_out, int out_size) {
    const float* user_table = (const float*)d_in[0];
    const float* ent_table  = (const float*)d_in[1];
    const float* rel_table  = (const float*)d_in[2];
    const float* w_ih0      = (const float*)d_in[3];
    const float* w_hh0      = (const float*)d_in[4];
    const float* b_ih0      = (const float*)d_in[5];
    const float* b_hh0      = (const float*)d_in[6];
    const float* w_ih1      = (const float*)d_in[7];
    const float* w_hh1      = (const float*)d_in[8];
    const float* b_ih1      = (const float*)d_in[9];
    const float* b_hh1      = (const float*)d_in[10];
    const float* agg_w      = (const float*)d_in[11];
    const float* agg_b      = (const float*)d_in[12];
    const int*   users      = (const int*)d_in[13];
    const int*   items      = (const int*)d_in[14];
    const int*   ratings    = (const int*)d_in[15];
    const int*   lp0        = (const int*)d_in[16];
    const int*   lp1        = (const int*)d_in[17];
    float*       out        = (float*)d_out;

    int B = in_sizes[13];

    precompute_tables_kernel<<<4, 1024>>>(rel_table, ent_table, w_ih0, w_ih1,
                                          b_ih0, b_hh0, b_ih1, b_hh1);
    precompute_u_kernel<<<NBLK, 256>>>(user_table, w_ih0, w_ih1,
                                       b_ih0, b_hh0, b_ih1, b_hh1, users, B);
    hop_mma_kernel<2, 3, 0><<<NBLK, 256>>>(w_hh0, items, lp0, B);
    hop_mma_kernel<3, 5, 1><<<NBLK, 256>>>(w_hh1, items, lp1, B);
    combine_kernel<<<NBLK, 256>>>(user_table, ent_table, agg_w, agg_b,
                                  users, items, ratings, out, B);
    loss_kernel<<<1, 512>>>(out, B, NBLK);
}

// round 9
// speedup vs baseline: 1.5116x; 1.1144x over previous
#include <cuda_runtime.h>
#include <math.h>
#include <stdint.h>

#define FULL 0xffffffffu
typedef unsigned long long u64;
typedef unsigned int u32;

static constexpr int P    = 16;
static constexpr int MAXB = 16384;
static constexpr int NBLK = 296;

// ---------------- scratch (__device__ globals; no allocations) ----------------
__device__ float4 g_Utab0[MAXB * 32];   // bias + u @ W_ih[:, :32]^T (bias folded)
__device__ float4 g_Utab1[MAXB * 32];
__device__ float4 g_Rtab0[32 * 32];     // bias + rel @ W_ih[:, :32]^T (bias folded)
__device__ float4 g_Etab0[32 * 32];     // ent @ W_ih[:, 32:]^T
__device__ float4 g_Rtab1[32 * 32];
__device__ float4 g_Etab1[32 * 32];
__device__ float4 g_RT0[1024 * 32];     // RT[ti*32+ri] = Rtab'[ri] + Etab[ti]
__device__ float4 g_RT1[1024 * 32];
__device__ float  g_final0[MAXB * 32];  // per-b summed h (complete)
__device__ float  g_final1[MAXB * 32];
__device__ float  g_lossblk[NBLK];

// ---------------- math helpers ----------------
__device__ __forceinline__ float tanha(float x) {
    float y; asm("tanh.approx.f32 %0,%1;" : "=f"(y) : "f"(x)); return y;
}
__device__ __forceinline__ float sigf(float x) {
    return fmaf(tanha(0.5f * x), 0.5f, 0.5f);
}
__device__ __forceinline__ u32 tf32r(float x) {
    u32 u; asm("cvt.rna.tf32.f32 %0,%1;" : "=r"(u) : "f"(x)); return u;
}
// D = A(16x8 tf32,row) @ B(8x8 tf32,col) + D   (f32 accum)
__device__ __forceinline__ void mma_tf32(float& d0, float& d1, float& d2, float& d3,
                                         u32 a0, u32 a1, u32 a2, u32 a3,
                                         u32 b0, u32 b1) {
    asm("mma.sync.aligned.m16n8k8.row.col.f32.tf32.tf32.f32 "
        "{%0,%1,%2,%3},{%4,%5,%6,%7},{%8,%9},{%0,%1,%2,%3};"
        : "+f"(d0), "+f"(d1), "+f"(d2), "+f"(d3)
        : "r"(a0), "r"(a1), "r"(a2), "r"(a3), "r"(b0), "r"(b1));
}

// ---------------- precompute E/R contribution tables (tiny) ----------------
__global__ void precompute_tables_kernel(const float* __restrict__ rel_table,
                                         const float* __restrict__ ent_table,
                                         const float* __restrict__ wih0,
                                         const float* __restrict__ wih1,
                                         const float* __restrict__ bih0,
                                         const float* __restrict__ bhh0,
                                         const float* __restrict__ bih1,
                                         const float* __restrict__ bhh1) {
    int tid   = threadIdx.x;          // 1024
    int which = blockIdx.x;           // 0:Rtab0 1:Etab0 2:Rtab1 3:Etab1
    int r     = tid >> 5;
    int lane  = tid & 31;
    const float* w   = (which < 2) ? wih0 : wih1;
    const float* src = (which & 1) ? ent_table : rel_table;
    int colofs       = (which & 1) ? 32 : 0;

    float4 acc = make_float4(0.f, 0.f, 0.f, 0.f);
    if (!(which & 1)) {  // Rtab: fold bias in
        const float* bi = (which < 2) ? bih0 : bih1;
        const float* bh = (which < 2) ? bhh0 : bhh1;
        acc.x = bi[lane]      + bh[lane];
        acc.y = bi[32 + lane] + bh[32 + lane];
        acc.z = bi[64 + lane] + bh[64 + lane];
        acc.w = bi[96 + lane] + bh[96 + lane];
    }
    #pragma unroll
    for (int k = 0; k < 32; k++) {
        float x = src[r * 32 + k];
        acc.x += x * w[(0 * 32 + lane) * 64 + colofs + k];
        acc.y += x * w[(1 * 32 + lane) * 64 + colofs + k];
        acc.z += x * w[(2 * 32 + lane) * 64 + colofs + k];
        acc.w += x * w[(3 * 32 + lane) * 64 + colofs + k];
    }
    float4* dst = (which == 0) ? g_Rtab0 : (which == 1) ? g_Etab0
                : (which == 2) ? g_Rtab1 : g_Etab1;
    dst[tid] = acc;
}

// ---------------- precompute fused RT tables: RT[ti*32+ri] = Rtab'[ri] + Etab[ti] ----------------
__global__ void precompute_rt_kernel() {
    int hop = blockIdx.y;
    int i = blockIdx.x * 256 + threadIdx.x;   // [0, 32768)
    int comb = i >> 5, j = i & 31;
    int t = comb >> 5, r = comb & 31;
    const float4* Rt = hop ? g_Rtab1 : g_Rtab0;
    const float4* Et = hop ? g_Etab1 : g_Etab0;
    float4 a = Rt[r * 32 + j], b = Et[t * 32 + j];
    float4 o = make_float4(a.x + b.x, a.y + b.y, a.z + b.z, a.w + b.w);
    (hop ? g_RT1 : g_RT0)[comb * 32 + j] = o;
}

// ---------------- precompute per-b user contribution (bias folded) ----------------
__global__ __launch_bounds__(256) void precompute_u_kernel(
        const float* __restrict__ user_table,
        const float* __restrict__ wih0,
        const float* __restrict__ wih1,
        const float* __restrict__ bih0,
        const float* __restrict__ bhh0,
        const float* __restrict__ bih1,
        const float* __restrict__ bhh1,
        const int* __restrict__ users, int B) {
    __shared__ float4 w0[32 * 32];
    __shared__ float4 w1[32 * 32];
    int tid = threadIdx.x;
    for (int i = tid; i < 32 * 32; i += 256) {
        int k = i >> 5, l = i & 31;
        w0[i] = make_float4(wih0[l * 64 + k], wih0[(l + 32) * 64 + k],
                            wih0[(l + 64) * 64 + k], wih0[(l + 96) * 64 + k]);
        w1[i] = make_float4(wih1[l * 64 + k], wih1[(l + 32) * 64 + k],
                            wih1[(l + 64) * 64 + k], wih1[(l + 96) * 64 + k]);
    }
    __syncthreads();

    int wid = tid >> 5, lane = tid & 31;
    float4 bias0 = make_float4(bih0[lane]      + bhh0[lane],
                               bih0[32 + lane] + bhh0[32 + lane],
                               bih0[64 + lane] + bhh0[64 + lane],
                               bih0[96 + lane] + bhh0[96 + lane]);
    float4 bias1 = make_float4(bih1[lane]      + bhh1[lane],
                               bih1[32 + lane] + bhh1[32 + lane],
                               bih1[64 + lane] + bhh1[64 + lane],
                               bih1[96 + lane] + bhh1[96 + lane]);

    int gw = blockIdx.x * 8 + wid, TW = gridDim.x * 8;
    for (int b = gw; b < B; b += TW) {
        float u = user_table[users[b] * 32 + lane];
        float4 a0 = bias0, a1 = bias1;
        #pragma unroll
        for (int k = 0; k < 32; k++) {
            float uk = __shfl_sync(FULL, u, k);
            float4 q0 = w0[k * 32 + lane];
            float4 q1 = w1[k * 32 + lane];
            a0.x += uk * q0.x; a0.y += uk * q0.y; a0.z += uk * q0.z; a0.w += uk * q0.w;
            a1.x += uk * q1.x; a1.y += uk * q1.y; a1.z += uk * q1.z; a1.w += uk * q1.w;
        }
        g_Utab0[b * 32 + lane] = a0;
        g_Utab1[b * 32 + lane] = a1;
    }
}

// ---------------- mma.sync hop kernel (K=32, fused RT table init) ----------------
// Warp = one batch row b (16 paths = M-tile). Recurrent step:
//   gates = RT[ti,ri] (D-accum init) + H[16x32] @ Whh^T[32x128] (tensor core)
template <int NSTEP, int STRIDE, int HOP>
__global__ __launch_bounds__(256, 2) void hop_mma_kernel(
        const float* __restrict__ whh,
        const int* __restrict__ items,
        const int* __restrict__ lp, int B) {
    // Fragment-ordered B (Whh only), 2 k-tiles per uint4:
    // Bs4[(kt2*16+nt)*32+lane] = {kt=2kt2: b0,b1, kt=2kt2+1: b0,b1}
    __shared__ uint4 Bs4[2 * 16 * 32];   // 16KB

    const float4* Etab4 = HOP ? g_Etab1 : g_Etab0;
    const float4* Utab4 = HOP ? g_Utab1 : g_Utab0;
    const float4* RTtab = HOP ? g_RT1 : g_RT0;
    float* gout = HOP ? g_final1 : g_final0;

    int tid = threadIdx.x;
    // ---- fill Bs4 (once per CTA) ----
    for (int i = tid; i < 2 * 16 * 32; i += 256) {
        int kt2 = i >> 9;
        int nt = (i >> 5) & 15;
        int ln = i & 31;
        int t = ln & 3, gq = ln >> 2;
        int g = 8 * nt + gq;
        int k0 = 8 * (2 * kt2) + t, k1 = 8 * (2 * kt2 + 1) + t;
        Bs4[i] = make_uint4(tf32r(whh[g * 32 + k0]), tf32r(whh[g * 32 + k0 + 4]),
                            tf32r(whh[g * 32 + k1]), tf32r(whh[g * 32 + k1 + 4]));
    }
    __syncthreads();

    int wid = tid >> 5, lane = tid & 31;
    int r0 = lane >> 2, t = lane & 3;
    int srcA = (r0 << 2) | (t >> 1);
    int srcB = srcA + 2;

    int gw = blockIdx.x * 8 + wid;
    int TW = NBLK * 8;

    for (int b = gw; b < B; b += TW) {
        int item = __ldg(&items[b]);
        // lanes 0..15 own path lane; pack 5-bit indices
        int p = lane & 15;
        const int* lpb = lp + (size_t)item * (P * STRIDE) + p * STRIDE;
        u32 ip = 0;
        #pragma unroll
        for (int j = 0; j < STRIDE; j++)
            ip |= ((u32)__ldg(&lpb[j])) << (5 * j);
        u32 idxA = __shfl_sync(FULL, ip, r0);       // path r0
        u32 idxB = __shfl_sync(FULL, ip, r0 + 8);   // path r0+8

        // ---- step 0 in D-fragment layout: gates = U'(bias) + E[seed] ----
        float c_st[16], h_d[16];   // flat = jt*4 + (path?2:0) + cc
        {
            const float4* Ut = Utab4 + (size_t)b * 32;
            const float4* EA = Etab4 + (idxA & 31) * 32;
            const float4* EB = Etab4 + (idxB & 31) * 32;
            #pragma unroll
            for (int jt = 0; jt < 4; jt++) {
                #pragma unroll
                for (int cc = 0; cc < 2; cc++) {
                    int j = 8 * jt + 2 * t + cc;
                    float4 u4 = Ut[j];
                    float4 e = EA[j];
                    float c0 = sigf(u4.x + e.x) * tanha(u4.z + e.z);
                    c_st[jt * 4 + cc] = c0;
                    h_d[jt * 4 + cc]  = sigf(u4.w + e.w) * tanha(c0);
                    e = EB[j];
                    c0 = sigf(u4.x + e.x) * tanha(u4.z + e.z);
                    c_st[jt * 4 + 2 + cc] = c0;
                    h_d[jt * 4 + 2 + cc]  = sigf(u4.w + e.w) * tanha(c0);
                }
            }
        }

        // ---- recurrent steps ----
        #pragma unroll
        for (int s = 1; s < NSTEP; s++) {
            // relayout h: D-frag -> A-frag via shuffles (kt 0..3)
            u32 aa[16];
            #pragma unroll
            for (int kt = 0; kt < 4; kt++) {
                float y0, y1;
                y0 = __shfl_sync(FULL, h_d[kt * 4 + 0], srcA);
                y1 = __shfl_sync(FULL, h_d[kt * 4 + 1], srcA);
                aa[kt * 4 + 0] = tf32r((t & 1) ? y1 : y0);
                y0 = __shfl_sync(FULL, h_d[kt * 4 + 2], srcA);
                y1 = __shfl_sync(FULL, h_d[kt * 4 + 3], srcA);
                aa[kt * 4 + 1] = tf32r((t & 1) ? y1 : y0);
                y0 = __shfl_sync(FULL, h_d[kt * 4 + 0], srcB);
                y1 = __shfl_sync(FULL, h_d[kt * 4 + 1], srcB);
                aa[kt * 4 + 2] = tf32r((t & 1) ? y1 : y0);
                y0 = __shfl_sync(FULL, h_d[kt * 4 + 2], srcB);
                y1 = __shfl_sync(FULL, h_d[kt * 4 + 3], srcB);
                aa[kt * 4 + 3] = tf32r((t & 1) ? y1 : y0);
            }

            // fused RT gather pointers (combined 10-bit index = ti*32 + ri)
            u32 cA = (idxA >> (5 * (2 * s - 1))) & 1023;
            u32 cB = (idxB >> (5 * (2 * s - 1))) & 1023;
            const float4* RTA = RTtab + cA * 32;
            const float4* RTB = RTtab + cB * 32;

            // per j-tile: init D from RT, MMA accumulate, activations
            #pragma unroll
            for (int jt = 0; jt < 4; jt++) {
                float G[4][4];   // [gate i/f/g/o][pp*2+cc]
                #pragma unroll
                for (int cc = 0; cc < 2; cc++) {
                    int j = 8 * jt + 2 * t + cc;
                    float4 ra = RTA[j];
                    G[0][cc] = ra.x; G[1][cc] = ra.y; G[2][cc] = ra.z; G[3][cc] = ra.w;
                    float4 rb = RTB[j];
                    G[0][2 + cc] = rb.x; G[1][2 + cc] = rb.y;
                    G[2][2 + cc] = rb.z; G[3][2 + cc] = rb.w;
                }
                #pragma unroll
                for (int gt = 0; gt < 4; gt++) {
                    int nt = jt + 4 * gt;
                    uint4 b01 = Bs4[(0 * 16 + nt) * 32 + lane];
                    uint4 b23 = Bs4[(1 * 16 + nt) * 32 + lane];
                    mma_tf32(G[gt][0], G[gt][1], G[gt][2], G[gt][3],
                             aa[0], aa[1], aa[2], aa[3], b01.x, b01.y);
                    mma_tf32(G[gt][0], G[gt][1], G[gt][2], G[gt][3],
                             aa[4], aa[5], aa[6], aa[7], b01.z, b01.w);
                    mma_tf32(G[gt][0], G[gt][1], G[gt][2], G[gt][3],
                             aa[8], aa[9], aa[10], aa[11], b23.x, b23.y);
                    mma_tf32(G[gt][0], G[gt][1], G[gt][2], G[gt][3],
                             aa[12], aa[13], aa[14], aa[15], b23.z, b23.w);
                }
                #pragma unroll
                for (int dq = 0; dq < 4; dq++) {
                    int ci = jt * 4 + dq;
                    float c = sigf(G[1][dq]) * c_st[ci] + sigf(G[0][dq]) * tanha(G[2][dq]);
                    c_st[ci] = c;
                    h_d[ci] = sigf(G[3][dq]) * tanha(c);
                }
            }
        }

        // ---- reduce 16 paths -> per-b sum, write ----
        #pragma unroll
        for (int jt = 0; jt < 4; jt++) {
            #pragma unroll
            for (int cc = 0; cc < 2; cc++) {
                float v = h_d[jt * 4 + cc] + h_d[jt * 4 + 2 + cc];
                v += __shfl_xor_sync(FULL, v, 4);
                v += __shfl_xor_sync(FULL, v, 8);
                v += __shfl_xor_sync(FULL, v, 16);
                if (lane < 4)
                    gout[b * 32 + 8 * jt + 2 * lane + cc] = v;
            }
        }
    }
}

// ---------------- combine: agg matmuls, scores, sigmoid, block loss partials ----------------
__global__ __launch_bounds__(256) void combine_kernel(
        const float* __restrict__ user_table,
        const float* __restrict__ ent_table,
        const float* __restrict__ agg_w,
        const float* __restrict__ agg_b,
        const int* __restrict__ users,
        const int* __restrict__ items,
        const int* __restrict__ ratings,
        float* __restrict__ out, int B) {
    __shared__ float aggT[32 * 32];
    __shared__ float aggb_sm[32];
    __shared__ float lred[8];
    int tid = threadIdx.x;
    for (int i = tid; i < 32 * 32; i += 256) {
        int k = i >> 5, j = i & 31;
        aggT[i] = agg_w[j * 32 + k];
    }
    if (tid < 32) aggb_sm[tid] = agg_b[tid];
    __syncthreads();

    int wid = tid >> 5, lane = tid & 31;
    int gw = blockIdx.x * 8 + wid, TW = gridDim.x * 8;
    float loss_acc = 0.f;

    for (int b = gw; b < B; b += TW) {
        int item = items[b];
        int user = users[b];

        float f0 = g_final0[b * 32 + lane];
        float f1 = g_final1[b * 32 + lane];

        float v = ent_table[item * 32 + lane] + f0;
        float acc = aggb_sm[lane];
        #pragma unroll
        for (int k = 0; k < 32; k++)
            acc += __shfl_sync(FULL, v, k) * aggT[k * 32 + lane];

        v = acc + f1;
        acc = aggb_sm[lane];
        #pragma unroll
        for (int k = 0; k < 32; k++)
            acc += __shfl_sync(FULL, v, k) * aggT[k * 32 + lane];

        float prod = user_table[user * 32 + lane] * acc;
        #pragma unroll
        for (int o = 16; o; o >>= 1) prod += __shfl_xor_sync(FULL, prod, o);

        if (lane == 0) {
            float s = prod;
            out[1 + b]     = 1.0f / (1.0f + __expf(-s));
            out[1 + B + b] = (float)item;
            float r    = (float)ratings[b];
            float ls_p = fminf(s, 0.0f)  - log1pf(__expf(-fabsf(s)));
            float ls_n = fminf(-s, 0.0f) - log1pf(__expf(-fabsf(s)));
            loss_acc += -(r * ls_p + (1.0f - r) * ls_n);
        }
    }

    if (lane == 0) lred[wid] = loss_acc;
    __syncthreads();
    if (tid == 0) {
        float s = 0.f;
        #pragma unroll
        for (int w = 0; w < 8; w++) s += lred[w];
        g_lossblk[blockIdx.x] = s;
    }
}

// ---------------- final loss reduction ----------------
__global__ void loss_kernel(float* __restrict__ out, int B, int nblk) {
    __shared__ float sm[512];
    int tid = threadIdx.x;
    float s = 0.f;
    for (int i = tid; i < nblk; i += 512) s += g_lossblk[i];
    sm[tid] = s;
    __syncthreads();
    for (int o = 256; o; o >>= 1) {
        if (tid < o) sm[tid] += sm[tid + o];
        __syncthreads();
    }
    if (tid == 0) out[0] = sm[0] / (float)B;
}

// ---------------- launch ----------------
extern "C" void kernel_launch(void* const* d_in, const int* in_sizes, int n_in,
                              void* d_out, int out_size) {
    const float* user_table = (const float*)d_in[0];
    const float* ent_table  = (const float*)d_in[1];
    const float* rel_table  = (const float*)d_in[2];
    const float* w_ih0      = (const float*)d_in[3];
    const float* w_hh0      = (const float*)d_in[4];
    const float* b_ih0      = (const float*)d_in[5];
    const float* b_hh0      = (const float*)d_in[6];
    const float* w_ih1      = (const float*)d_in[7];
    const float* w_hh1      = (const float*)d_in[8];
    const float* b_ih1      = (const float*)d_in[9];
    const float* b_hh1      = (const float*)d_in[10];
    const float* agg_w      = (const float*)d_in[11];
    const float* agg_b      = (const float*)d_in[12];
    const int*   users      = (const int*)d_in[13];
    const int*   items      = (const int*)d_in[14];
    const int*   ratings    = (const int*)d_in[15];
    const int*   lp0        = (const int*)d_in[16];
    const int*   lp1        = (const int*)d_in[17];
    float*       out        = (float*)d_out;

    int B = in_sizes[13];

    precompute_tables_kernel<<<4, 1024>>>(rel_table, ent_table, w_ih0, w_ih1,
                                          b_ih0, b_hh0, b_ih1, b_hh1);
    precompute_rt_kernel<<<dim3(128, 2), 256>>>();
    precompute_u_kernel<<<NBLK, 256>>>(user_table, w_ih0, w_ih1,
                                       b_ih0, b_hh0, b_ih1, b_hh1, users, B);
    hop_mma_kernel<2, 3, 0><<<NBLK, 256>>>(w_hh0, items, lp0, B);
    hop_mma_kernel<3, 5, 1><<<NBLK, 256>>>(w_hh1, items, lp1, B);
    combine_kernel<<<NBLK, 256>>>(user_table, ent_table, agg_w, agg_b,
                                  users, items, ratings, out, B);
    loss_kernel<<<1, 512>>>(out, B, NBLK);
}

// round 10
// speedup vs baseline: 1.8529x; 1.2258x over previous
#include <cuda_runtime.h>
#include <math.h>
#include <stdint.h>

#define FULL 0xffffffffu
typedef unsigned long long u64;
typedef unsigned int u32;

static constexpr int P    = 16;
static constexpr int MAXB = 16384;
static constexpr int NBLK = 296;

// ---------------- scratch (__device__ globals; no allocations) ----------------
__device__ float4 g_Utab0[MAXB * 32];   // bias + u @ W_ih[:, :32]^T (bias folded)
__device__ float4 g_Utab1[MAXB * 32];
__device__ float4 g_Rtab0[32 * 32];     // bias + rel @ W_ih[:, :32]^T (bias folded)
__device__ float4 g_Etab0[32 * 32];     // ent @ W_ih[:, 32:]^T
__device__ float4 g_Rtab1[32 * 32];
__device__ float4 g_Etab1[32 * 32];
__device__ float4 g_RT0[1024 * 32];     // RT[ti*32+ri] = Rtab'[ri] + Etab[ti]
__device__ float4 g_RT1[1024 * 32];
__device__ float  g_final0[MAXB * 32];  // per-b summed h (complete)
__device__ float  g_final1[MAXB * 32];
__device__ float  g_lossblk[NBLK];

// ---------------- math helpers ----------------
__device__ __forceinline__ float tanha(float x) {
    float y; asm("tanh.approx.f32 %0,%1;" : "=f"(y) : "f"(x)); return y;
}
__device__ __forceinline__ float sigf(float x) {
    return fmaf(tanha(0.5f * x), 0.5f, 0.5f);
}
// pack {lo, hi} into bf16x2 (PTX: first source -> high half)
__device__ __forceinline__ u32 bfpack(float lo, float hi) {
    u32 d; asm("cvt.rn.bf16x2.f32 %0,%1,%2;" : "=r"(d) : "f"(hi), "f"(lo)); return d;
}
// D(16x8 f32) += A(16x16 bf16,row) @ B(16x8 bf16,col)
__device__ __forceinline__ void mma_bf16(float& d0, float& d1, float& d2, float& d3,
                                         u32 a0, u32 a1, u32 a2, u32 a3,
                                         u32 b0, u32 b1) {
    asm("mma.sync.aligned.m16n8k16.row.col.f32.bf16.bf16.f32 "
        "{%0,%1,%2,%3},{%4,%5,%6,%7},{%8,%9},{%0,%1,%2,%3};"
        : "+f"(d0), "+f"(d1), "+f"(d2), "+f"(d3)
        : "r"(a0), "r"(a1), "r"(a2), "r"(a3), "r"(b0), "r"(b1));
}

// ---------------- precompute E/R contribution tables (tiny) ----------------
__global__ void precompute_tables_kernel(const float* __restrict__ rel_table,
                                         const float* __restrict__ ent_table,
                                         const float* __restrict__ wih0,
                                         const float* __restrict__ wih1,
                                         const float* __restrict__ bih0,
                                         const float* __restrict__ bhh0,
                                         const float* __restrict__ bih1,
                                         const float* __restrict__ bhh1) {
    int tid   = threadIdx.x;          // 1024
    int which = blockIdx.x;           // 0:Rtab0 1:Etab0 2:Rtab1 3:Etab1
    int r     = tid >> 5;
    int lane  = tid & 31;
    const float* w   = (which < 2) ? wih0 : wih1;
    const float* src = (which & 1) ? ent_table : rel_table;
    int colofs       = (which & 1) ? 32 : 0;

    float4 acc = make_float4(0.f, 0.f, 0.f, 0.f);
    if (!(which & 1)) {  // Rtab: fold bias in
        const float* bi = (which < 2) ? bih0 : bih1;
        const float* bh = (which < 2) ? bhh0 : bhh1;
        acc.x = bi[lane]      + bh[lane];
        acc.y = bi[32 + lane] + bh[32 + lane];
        acc.z = bi[64 + lane] + bh[64 + lane];
        acc.w = bi[96 + lane] + bh[96 + lane];
    }
    #pragma unroll
    for (int k = 0; k < 32; k++) {
        float x = src[r * 32 + k];
        acc.x += x * w[(0 * 32 + lane) * 64 + colofs + k];
        acc.y += x * w[(1 * 32 + lane) * 64 + colofs + k];
        acc.z += x * w[(2 * 32 + lane) * 64 + colofs + k];
        acc.w += x * w[(3 * 32 + lane) * 64 + colofs + k];
    }
    float4* dst = (which == 0) ? g_Rtab0 : (which == 1) ? g_Etab0
                : (which == 2) ? g_Rtab1 : g_Etab1;
    dst[tid] = acc;
}

// ---------------- precompute fused RT tables: RT[ti*32+ri] = Rtab'[ri] + Etab[ti] ----------------
__global__ void precompute_rt_kernel() {
    int hop = blockIdx.y;
    int i = blockIdx.x * 256 + threadIdx.x;   // [0, 32768)
    int comb = i >> 5, j = i & 31;
    int t = comb >> 5, r = comb & 31;
    const float4* Rt = hop ? g_Rtab1 : g_Rtab0;
    const float4* Et = hop ? g_Etab1 : g_Etab0;
    float4 a = Rt[r * 32 + j], b = Et[t * 32 + j];
    float4 o = make_float4(a.x + b.x, a.y + b.y, a.z + b.z, a.w + b.w);
    (hop ? g_RT1 : g_RT0)[comb * 32 + j] = o;
}

// ---------------- precompute per-b user contribution (bias folded) ----------------
__global__ __launch_bounds__(256) void precompute_u_kernel(
        const float* __restrict__ user_table,
        const float* __restrict__ wih0,
        const float* __restrict__ wih1,
        const float* __restrict__ bih0,
        const float* __restrict__ bhh0,
        const float* __restrict__ bih1,
        const float* __restrict__ bhh1,
        const int* __restrict__ users, int B) {
    __shared__ float4 w0[32 * 32];
    __shared__ float4 w1[32 * 32];
    int tid = threadIdx.x;
    for (int i = tid; i < 32 * 32; i += 256) {
        int k = i >> 5, l = i & 31;
        w0[i] = make_float4(wih0[l * 64 + k], wih0[(l + 32) * 64 + k],
                            wih0[(l + 64) * 64 + k], wih0[(l + 96) * 64 + k]);
        w1[i] = make_float4(wih1[l * 64 + k], wih1[(l + 32) * 64 + k],
                            wih1[(l + 64) * 64 + k], wih1[(l + 96) * 64 + k]);
    }
    __syncthreads();

    int wid = tid >> 5, lane = tid & 31;
    float4 bias0 = make_float4(bih0[lane]      + bhh0[lane],
                               bih0[32 + lane] + bhh0[32 + lane],
                               bih0[64 + lane] + bhh0[64 + lane],
                               bih0[96 + lane] + bhh0[96 + lane]);
    float4 bias1 = make_float4(bih1[lane]      + bhh1[lane],
                               bih1[32 + lane] + bhh1[32 + lane],
                               bih1[64 + lane] + bhh1[64 + lane],
                               bih1[96 + lane] + bhh1[96 + lane]);

    int gw = blockIdx.x * 8 + wid, TW = gridDim.x * 8;
    for (int b = gw; b < B; b += TW) {
        float u = user_table[users[b] * 32 + lane];
        float4 a0 = bias0, a1 = bias1;
        #pragma unroll
        for (int k = 0; k < 32; k++) {
            float uk = __shfl_sync(FULL, u, k);
            float4 q0 = w0[k * 32 + lane];
            float4 q1 = w1[k * 32 + lane];
            a0.x += uk * q0.x; a0.y += uk * q0.y; a0.z += uk * q0.z; a0.w += uk * q0.w;
            a1.x += uk * q1.x; a1.y += uk * q1.y; a1.z += uk * q1.z; a1.w += uk * q1.w;
        }
        g_Utab0[b * 32 + lane] = a0;
        g_Utab1[b * 32 + lane] = a1;
    }
}

// ---------------- bf16 mma hop kernel ----------------
// Warp = one batch row b (16 paths = M-tile). Recurrent step:
//   gates = RT[ti,ri] (D init) + H[16x32]bf16 @ Whh^T[32x128]bf16  (m16n8k16)
// Key: bf16 D-fragment layout == A-fragment layout -> NO cross-lane relayout.
template <int NSTEP, int STRIDE, int HOP>
__global__ __launch_bounds__(256, 2) void hop_mma_kernel(
        const float* __restrict__ whh,
        const int* __restrict__ items,
        const int* __restrict__ lp, int B) {
    // Fragment-ordered bf16 B: Bs2[nt*32+lane] = {m0.b0, m0.b1, m1.b0, m1.b1}
    // m = k16-MMA index (k = 16m..16m+15); b0: k=16m+2t,+1; b1: k=16m+8+2t,+1; col g=8nt+gq
    __shared__ uint4 Bs2[16 * 32];   // 8KB

    const float4* Etab4 = HOP ? g_Etab1 : g_Etab0;
    const float4* Utab4 = HOP ? g_Utab1 : g_Utab0;
    const float4* RTtab = HOP ? g_RT1 : g_RT0;
    float* gout = HOP ? g_final1 : g_final0;

    int tid = threadIdx.x;
    // ---- fill Bs2 (once per CTA) ----
    for (int i = tid; i < 16 * 32; i += 256) {
        int nt = i >> 5;
        int ln = i & 31;
        int t = ln & 3, gq = ln >> 2;
        const float* wg = whh + (8 * nt + gq) * 32;
        Bs2[i] = make_uint4(bfpack(wg[2 * t],      wg[2 * t + 1]),
                            bfpack(wg[2 * t + 8],  wg[2 * t + 9]),
                            bfpack(wg[2 * t + 16], wg[2 * t + 17]),
                            bfpack(wg[2 * t + 24], wg[2 * t + 25]));
    }
    __syncthreads();

    int wid = tid >> 5, lane = tid & 31;
    int r0 = lane >> 2, t = lane & 3;

    int gw = blockIdx.x * 8 + wid;
    int TW = NBLK * 8;

    for (int b = gw; b < B; b += TW) {
        int item = __ldg(&items[b]);
        // lanes 0..15 own path lane; pack 5-bit indices
        int p = lane & 15;
        const int* lpb = lp + (size_t)item * (P * STRIDE) + p * STRIDE;
        u32 ip = 0;
        #pragma unroll
        for (int j = 0; j < STRIDE; j++)
            ip |= ((u32)__ldg(&lpb[j])) << (5 * j);
        u32 idxA = __shfl_sync(FULL, ip, r0);       // path r0
        u32 idxB = __shfl_sync(FULL, ip, r0 + 8);   // path r0+8

        // ---- step 0 in D-fragment layout: gates = U'(bias) + E[seed] ----
        float c_st[16], h_d[16];   // flat = jt*4 + (pathB?2:0) + cc
        {
            const float4* Ut = Utab4 + (size_t)b * 32;
            const float4* EA = Etab4 + (idxA & 31) * 32;
            const float4* EB = Etab4 + (idxB & 31) * 32;
            #pragma unroll
            for (int jt = 0; jt < 4; jt++) {
                #pragma unroll
                for (int cc = 0; cc < 2; cc++) {
                    int j = 8 * jt + 2 * t + cc;
                    float4 u4 = Ut[j];
                    float4 e = EA[j];
                    float c0 = sigf(u4.x + e.x) * tanha(u4.z + e.z);
                    c_st[jt * 4 + cc] = c0;
                    h_d[jt * 4 + cc]  = sigf(u4.w + e.w) * tanha(c0);
                    e = EB[j];
                    c0 = sigf(u4.x + e.x) * tanha(u4.z + e.z);
                    c_st[jt * 4 + 2 + cc] = c0;
                    h_d[jt * 4 + 2 + cc]  = sigf(u4.w + e.w) * tanha(c0);
                }
            }
        }

        // ---- recurrent steps ----
        #pragma unroll
        for (int s = 1; s < NSTEP; s++) {
            // D-frag -> A-frag: SAME LANE for bf16 k16; just pack pairs.
            // MMA0 (k0..15):  a0=(h[r0][2t],h[r0][2t+1])=jt0 d0,d1; a1=jt0 d2,d3 (row+8);
            //                 a2=jt1 d0,d1; a3=jt1 d2,d3
            // MMA1 (k16..31): jt2, jt3 likewise.
            u32 ah[8];
            #pragma unroll
            for (int q = 0; q < 8; q++)
                ah[q] = bfpack(h_d[q * 2], h_d[q * 2 + 1]);

            // fused RT gather pointers (combined 10-bit index = ti*32 + ri)
            u32 cA = (idxA >> (5 * (2 * s - 1))) & 1023;
            u32 cB = (idxB >> (5 * (2 * s - 1))) & 1023;
            const float4* RTA = RTtab + cA * 32;
            const float4* RTB = RTtab + cB * 32;

            // per j-tile: init D from RT, 2 bf16 MMAs per n-tile, activations
            #pragma unroll
            for (int jt = 0; jt < 4; jt++) {
                float G[4][4];   // [gate i/f/g/o][pp*2+cc]
                #pragma unroll
                for (int cc = 0; cc < 2; cc++) {
                    int j = 8 * jt + 2 * t + cc;
                    float4 ra = RTA[j];
                    G[0][cc] = ra.x; G[1][cc] = ra.y; G[2][cc] = ra.z; G[3][cc] = ra.w;
                    float4 rb = RTB[j];
                    G[0][2 + cc] = rb.x; G[1][2 + cc] = rb.y;
                    G[2][2 + cc] = rb.z; G[3][2 + cc] = rb.w;
                }
                #pragma unroll
                for (int gt = 0; gt < 4; gt++) {
                    int nt = jt + 4 * gt;
                    uint4 bb = Bs2[nt * 32 + lane];
                    mma_bf16(G[gt][0], G[gt][1], G[gt][2], G[gt][3],
                             ah[0], ah[1], ah[2], ah[3], bb.x, bb.y);
                    mma_bf16(G[gt][0], G[gt][1], G[gt][2], G[gt][3],
                             ah[4], ah[5], ah[6], ah[7], bb.z, bb.w);
                }
                #pragma unroll
                for (int dq = 0; dq < 4; dq++) {
                    int ci = jt * 4 + dq;
                    float c = sigf(G[1][dq]) * c_st[ci] + sigf(G[0][dq]) * tanha(G[2][dq]);
                    c_st[ci] = c;
                    h_d[ci] = sigf(G[3][dq]) * tanha(c);
                }
            }
        }

        // ---- reduce 16 paths -> per-b sum, write ----
        #pragma unroll
        for (int jt = 0; jt < 4; jt++) {
            #pragma unroll
            for (int cc = 0; cc < 2; cc++) {
                float v = h_d[jt * 4 + cc] + h_d[jt * 4 + 2 + cc];
                v += __shfl_xor_sync(FULL, v, 4);
                v += __shfl_xor_sync(FULL, v, 8);
                v += __shfl_xor_sync(FULL, v, 16);
                if (lane < 4)
                    gout[b * 32 + 8 * jt + 2 * lane + cc] = v;
            }
        }
    }
}

// ---------------- combine: agg matmuls, scores, sigmoid, block loss partials ----------------
__global__ __launch_bounds__(256) void combine_kernel(
        const float* __restrict__ user_table,
        const float* __restrict__ ent_table,
        const float* __restrict__ agg_w,
        const float* __restrict__ agg_b,
        const int* __restrict__ users,
        const int* __restrict__ items,
        const int* __restrict__ ratings,
        float* __restrict__ out, int B) {
    __shared__ float aggT[32 * 32];
    __shared__ float aggb_sm[32];
    __shared__ float lred[8];
    int tid = threadIdx.x;
    for (int i = tid; i < 32 * 32; i += 256) {
        int k = i >> 5, j = i & 31;
        aggT[i] = agg_w[j * 32 + k];
    }
    if (tid < 32) aggb_sm[tid] = agg_b[tid];
    __syncthreads();

    int wid = tid >> 5, lane = tid & 31;
    int gw = blockIdx.x * 8 + wid, TW = gridDim.x * 8;
    float loss_acc = 0.f;

    for (int b = gw; b < B; b += TW) {
        int item = items[b];
        int user = users[b];

        float f0 = g_final0[b * 32 + lane];
        float f1 = g_final1[b * 32 + lane];

        float v = ent_table[item * 32 + lane] + f0;
        float acc = aggb_sm[lane];
        #pragma unroll
        for (int k = 0; k < 32; k++)
            acc += __shfl_sync(FULL, v, k) * aggT[k * 32 + lane];

        v = acc + f1;
        acc = aggb_sm[lane];
        #pragma unroll
        for (int k = 0; k < 32; k++)
            acc += __shfl_sync(FULL, v, k) * aggT[k * 32 + lane];

        float prod = user_table[user * 32 + lane] * acc;
        #pragma unroll
        for (int o = 16; o; o >>= 1) prod += __shfl_xor_sync(FULL, prod, o);

        if (lane == 0) {
            float s = prod;
            out[1 + b]     = 1.0f / (1.0f + __expf(-s));
            out[1 + B + b] = (float)item;
            float r    = (float)ratings[b];
            float ls_p = fminf(s, 0.0f)  - log1pf(__expf(-fabsf(s)));
            float ls_n = fminf(-s, 0.0f) - log1pf(__expf(-fabsf(s)));
            loss_acc += -(r * ls_p + (1.0f - r) * ls_n);
        }
    }

    if (lane == 0) lred[wid] = loss_acc;
    __syncthreads();
    if (tid == 0) {
        float s = 0.f;
        #pragma unroll
        for (int w = 0; w < 8; w++) s += lred[w];
        g_lossblk[blockIdx.x] = s;
    }
}

// ---------------- final loss reduction ----------------
__global__ void loss_kernel(float* __restrict__ out, int B, int nblk) {
    __shared__ float sm[512];
    int tid = threadIdx.x;
    float s = 0.f;
    for (int i = tid; i < nblk; i += 512) s += g_lossblk[i];
    sm[tid] = s;
    __syncthreads();
    for (int o = 256; o; o >>= 1) {
        if (tid < o) sm[tid] += sm[tid + o];
        __syncthreads();
    }
    if (tid == 0) out[0] = sm[0] / (float)B;
}

// ---------------- launch ----------------
extern "C" void kernel_launch(void* const* d_in, const int* in_sizes, int n_in,
                              void* d_out, int out_size) {
    const float* user_table = (const float*)d_in[0];
    const float* ent_table  = (const float*)d_in[1];
    const float* rel_table  = (const float*)d_in[2];
    const float* w_ih0      = (const float*)d_in[3];
    const float* w_hh0      = (const float*)d_in[4];
    const float* b_ih0      = (const float*)d_in[5];
    const float* b_hh0      = (const float*)d_in[6];
    const float* w_ih1      = (const float*)d_in[7];
    const float* w_hh1      = (const float*)d_in[8];
    const float* b_ih1      = (const float*)d_in[9];
    const float* b_hh1      = (const float*)d_in[10];
    const float* agg_w      = (const float*)d_in[11];
    const float* agg_b      = (const float*)d_in[12];
    const int*   users      = (const int*)d_in[13];
    const int*   items      = (const int*)d_in[14];
    const int*   ratings    = (const int*)d_in[15];
    const int*   lp0        = (const int*)d_in[16];
    const int*   lp1        = (const int*)d_in[17];
    float*       out        = (float*)d_out;

    int B = in_sizes[13];

    precompute_tables_kernel<<<4, 1024>>>(rel_table, ent_table, w_ih0, w_ih1,
                                          b_ih0, b_hh0, b_ih1, b_hh1);
    precompute_rt_kernel<<<dim3(128, 2), 256>>>();
    precompute_u_kernel<<<NBLK, 256>>>(user_table, w_ih0, w_ih1,
                                       b_ih0, b_hh0, b_ih1, b_hh1, users, B);
    hop_mma_kernel<2, 3, 0><<<NBLK, 256>>>(w_hh0, items, lp0, B);
    hop_mma_kernel<3, 5, 1><<<NBLK, 256>>>(w_hh1, items, lp1, B);
    combine_kernel<<<NBLK, 256>>>(user_table, ent_table, agg_w, agg_b,
                                  users, items, ratings, out, B);
    loss_kernel<<<1, 512>>>(out, B, NBLK);
}

// round 11
// speedup vs baseline: 2.0929x; 1.1295x over previous
#include <cuda_runtime.h>
#include <math.h>
#include <stdint.h>

#define FULL 0xffffffffu
typedef unsigned long long u64;
typedef unsigned int u32;

static constexpr int P    = 16;
static constexpr int MAXB = 16384;
static constexpr int NBLK = 296;

// ---------------- scratch (__device__ globals; no allocations) ----------------
__device__ float4 g_Rtab0[32 * 32];     // rel @ W_ih[:, :32]^T           (no bias)
__device__ float4 g_Etab0[32 * 32];     // bias + ent @ W_ih[:, 32:]^T    (bias folded)
__device__ float4 g_Rtab1[32 * 32];
__device__ float4 g_Etab1[32 * 32];
__device__ float4 g_RT0[1024 * 32];     // RT[ti*32+ri] = Rtab[ri] + Etab'[ti] (bias once)
__device__ float4 g_RT1[1024 * 32];
__device__ float  g_final0[MAXB * 32];  // per-b summed h (complete)
__device__ float  g_final1[MAXB * 32];
__device__ float  g_lossblk[NBLK];

// ---------------- math helpers ----------------
__device__ __forceinline__ float tanha(float x) {
    float y; asm("tanh.approx.f32 %0,%1;" : "=f"(y) : "f"(x)); return y;
}
__device__ __forceinline__ float sigf(float x) {
    return fmaf(tanha(0.5f * x), 0.5f, 0.5f);
}
// pack {lo, hi} into bf16x2 (PTX: first source -> high half)
__device__ __forceinline__ u32 bfpack(float lo, float hi) {
    u32 d; asm("cvt.rn.bf16x2.f32 %0,%1,%2;" : "=r"(d) : "f"(hi), "f"(lo)); return d;
}
// D(16x8 f32) += A(16x16 bf16,row) @ B(16x8 bf16,col)
__device__ __forceinline__ void mma_bf16(float& d0, float& d1, float& d2, float& d3,
                                         u32 a0, u32 a1, u32 a2, u32 a3,
                                         u32 b0, u32 b1) {
    asm("mma.sync.aligned.m16n8k16.row.col.f32.bf16.bf16.f32 "
        "{%0,%1,%2,%3},{%4,%5,%6,%7},{%8,%9},{%0,%1,%2,%3};"
        : "+f"(d0), "+f"(d1), "+f"(d2), "+f"(d3)
        : "r"(a0), "r"(a1), "r"(a2), "r"(a3), "r"(b0), "r"(b1));
}

// ---------------- precompute E/R contribution tables (tiny) ----------------
// bias now folded into ETAB (so step-0 seed gather carries it; RT sum unchanged)
__global__ void precompute_tables_kernel(const float* __restrict__ rel_table,
                                         const float* __restrict__ ent_table,
                                         const float* __restrict__ wih0,
                                         const float* __restrict__ wih1,
                                         const float* __restrict__ bih0,
                                         const float* __restrict__ bhh0,
                                         const float* __restrict__ bih1,
                                         const float* __restrict__ bhh1) {
    int tid   = threadIdx.x;          // 1024
    int which = blockIdx.x;           // 0:Rtab0 1:Etab0 2:Rtab1 3:Etab1
    int r     = tid >> 5;
    int lane  = tid & 31;
    const float* w   = (which < 2) ? wih0 : wih1;
    const float* src = (which & 1) ? ent_table : rel_table;
    int colofs       = (which & 1) ? 32 : 0;

    float4 acc = make_float4(0.f, 0.f, 0.f, 0.f);
    if (which & 1) {  // Etab: fold bias in
        const float* bi = (which < 2) ? bih0 : bih1;
        const float* bh = (which < 2) ? bhh0 : bhh1;
        acc.x = bi[lane]      + bh[lane];
        acc.y = bi[32 + lane] + bh[32 + lane];
        acc.z = bi[64 + lane] + bh[64 + lane];
        acc.w = bi[96 + lane] + bh[96 + lane];
    }
    #pragma unroll
    for (int k = 0; k < 32; k++) {
        float x = src[r * 32 + k];
        acc.x += x * w[(0 * 32 + lane) * 64 + colofs + k];
        acc.y += x * w[(1 * 32 + lane) * 64 + colofs + k];
        acc.z += x * w[(2 * 32 + lane) * 64 + colofs + k];
        acc.w += x * w[(3 * 32 + lane) * 64 + colofs + k];
    }
    float4* dst = (which == 0) ? g_Rtab0 : (which == 1) ? g_Etab0
                : (which == 2) ? g_Rtab1 : g_Etab1;
    dst[tid] = acc;
}

// ---------------- precompute fused RT tables: RT[ti*32+ri] = Rtab[ri] + Etab'[ti] ----------------
__global__ void precompute_rt_kernel() {
    int hop = blockIdx.y;
    int i = blockIdx.x * 256 + threadIdx.x;   // [0, 32768)
    int comb = i >> 5, j = i & 31;
    int t = comb >> 5, r = comb & 31;
    const float4* Rt = hop ? g_Rtab1 : g_Rtab0;
    const float4* Et = hop ? g_Etab1 : g_Etab0;
    float4 a = Rt[r * 32 + j], b = Et[t * 32 + j];
    float4 o = make_float4(a.x + b.x, a.y + b.y, a.z + b.z, a.w + b.w);
    (hop ? g_RT1 : g_RT0)[comb * 32 + j] = o;
}

// ---------------- bf16 mma hop kernel (U-term fused as broadcast MMA) ----------------
// Warp = one batch row b (16 paths = M-tile).
//   step 0:    gates = Etab'[seed] (D init, bias folded) + u_bcast[16x32] @ Wih_u^T (MMA)
//   steps s>0: gates = RT[ti,ri]   (D init)              + H[16x32]      @ Whh^T   (MMA)
template <int NSTEP, int STRIDE, int HOP>
__global__ __launch_bounds__(256, 2) void hop_mma_kernel(
        const float* __restrict__ whh,
        const float* __restrict__ wih,
        const float* __restrict__ user_table,
        const int* __restrict__ users,
        const int* __restrict__ items,
        const int* __restrict__ lp, int B) {
    // Fragment-ordered bf16 B tables: {m0.b0, m0.b1, m1.b0, m1.b1} per (nt,lane)
    __shared__ uint4 Bs2[16 * 32];   // Whh^T   (8KB)
    __shared__ uint4 BsU[16 * 32];   // Wih_u^T (8KB)

    const float4* Etab4 = HOP ? g_Etab1 : g_Etab0;
    const float4* RTtab = HOP ? g_RT1 : g_RT0;
    float* gout = HOP ? g_final1 : g_final0;

    int tid = threadIdx.x;
    // ---- fill Bs2 + BsU (once per CTA) ----
    for (int i = tid; i < 16 * 32; i += 256) {
        int nt = i >> 5;
        int ln = i & 31;
        int t = ln & 3, gq = ln >> 2;
        const float* wg = whh + (8 * nt + gq) * 32;
        Bs2[i] = make_uint4(bfpack(wg[2 * t],      wg[2 * t + 1]),
                            bfpack(wg[2 * t + 8],  wg[2 * t + 9]),
                            bfpack(wg[2 * t + 16], wg[2 * t + 17]),
                            bfpack(wg[2 * t + 24], wg[2 * t + 25]));
        const float* ug = wih + (8 * nt + gq) * 64;   // user half: cols 0..31
        BsU[i] = make_uint4(bfpack(ug[2 * t],      ug[2 * t + 1]),
                            bfpack(ug[2 * t + 8],  ug[2 * t + 9]),
                            bfpack(ug[2 * t + 16], ug[2 * t + 17]),
                            bfpack(ug[2 * t + 24], ug[2 * t + 25]));
    }
    __syncthreads();

    int wid = tid >> 5, lane = tid & 31;
    int r0 = lane >> 2, t = lane & 3;

    int gw = blockIdx.x * 8 + wid;
    int TW = NBLK * 8;

    for (int b = gw; b < B; b += TW) {
        int item = __ldg(&items[b]);
        // lanes 0..15 own path lane; pack 5-bit indices
        int p = lane & 15;
        const int* lpb = lp + (size_t)item * (P * STRIDE) + p * STRIDE;
        u32 ip = 0;
        #pragma unroll
        for (int j = 0; j < STRIDE; j++)
            ip |= ((u32)__ldg(&lpb[j])) << (5 * j);
        u32 idxA = __shfl_sync(FULL, ip, r0);       // path r0
        u32 idxB = __shfl_sync(FULL, ip, r0 + 8);   // path r0+8

        // u fragments: all 16 rows share u -> a(row)=a(row+8)
        const float* uptr = user_table + (size_t)__ldg(&users[b]) * 32;
        float2 uv0 = *(const float2*)(uptr + 2 * t);
        float2 uv1 = *(const float2*)(uptr + 2 * t + 8);
        float2 uv2 = *(const float2*)(uptr + 2 * t + 16);
        float2 uv3 = *(const float2*)(uptr + 2 * t + 24);
        u32 au0 = bfpack(uv0.x, uv0.y), au1 = bfpack(uv1.x, uv1.y);
        u32 au2 = bfpack(uv2.x, uv2.y), au3 = bfpack(uv3.x, uv3.y);

        // ---- step 0: D init = Etab'[seed] (bias folded), U-term via MMA ----
        float c_st[16], h_d[16];   // flat = jt*4 + (pathB?2:0) + cc
        {
            const float4* EA = Etab4 + (idxA & 31) * 32;
            const float4* EB = Etab4 + (idxB & 31) * 32;
            #pragma unroll
            for (int jt = 0; jt < 4; jt++) {
                float G[4][4];
                #pragma unroll
                for (int cc = 0; cc < 2; cc++) {
                    int j = 8 * jt + 2 * t + cc;
                    float4 ea = EA[j];
                    G[0][cc] = ea.x; G[1][cc] = ea.y; G[2][cc] = ea.z; G[3][cc] = ea.w;
                    float4 eb = EB[j];
                    G[0][2 + cc] = eb.x; G[1][2 + cc] = eb.y;
                    G[2][2 + cc] = eb.z; G[3][2 + cc] = eb.w;
                }
                #pragma unroll
                for (int gt = 0; gt < 4; gt++) {
                    int nt = jt + 4 * gt;
                    uint4 bu = BsU[nt * 32 + lane];
                    mma_bf16(G[gt][0], G[gt][1], G[gt][2], G[gt][3],
                             au0, au0, au1, au1, bu.x, bu.y);
                    mma_bf16(G[gt][0], G[gt][1], G[gt][2], G[gt][3],
                             au2, au2, au3, au3, bu.z, bu.w);
                }
                #pragma unroll
                for (int dq = 0; dq < 4; dq++) {
                    int ci = jt * 4 + dq;
                    float c = sigf(G[0][dq]) * tanha(G[2][dq]);   // c_prev = 0
                    c_st[ci] = c;
                    h_d[ci] = sigf(G[3][dq]) * tanha(c);
                }
            }
        }

        // ---- recurrent steps ----
        #pragma unroll
        for (int s = 1; s < NSTEP; s++) {
            // D-frag == A-frag for bf16 k16: same-lane packs only
            u32 ah[8];
            #pragma unroll
            for (int q = 0; q < 8; q++)
                ah[q] = bfpack(h_d[q * 2], h_d[q * 2 + 1]);

            // fused RT gather pointers (combined 10-bit index = ti*32 + ri)
            u32 cA = (idxA >> (5 * (2 * s - 1))) & 1023;
            u32 cB = (idxB >> (5 * (2 * s - 1))) & 1023;
            const float4* RTA = RTtab + cA * 32;
            const float4* RTB = RTtab + cB * 32;

            #pragma unroll
            for (int jt = 0; jt < 4; jt++) {
                float G[4][4];   // [gate i/f/g/o][pp*2+cc]
                #pragma unroll
                for (int cc = 0; cc < 2; cc++) {
                    int j = 8 * jt + 2 * t + cc;
                    float4 ra = RTA[j];
                    G[0][cc] = ra.x; G[1][cc] = ra.y; G[2][cc] = ra.z; G[3][cc] = ra.w;
                    float4 rb = RTB[j];
                    G[0][2 + cc] = rb.x; G[1][2 + cc] = rb.y;
                    G[2][2 + cc] = rb.z; G[3][2 + cc] = rb.w;
                }
                #pragma unroll
                for (int gt = 0; gt < 4; gt++) {
                    int nt = jt + 4 * gt;
                    uint4 bb = Bs2[nt * 32 + lane];
                    mma_bf16(G[gt][0], G[gt][1], G[gt][2], G[gt][3],
                             ah[0], ah[1], ah[2], ah[3], bb.x, bb.y);
                    mma_bf16(G[gt][0], G[gt][1], G[gt][2], G[gt][3],
                             ah[4], ah[5], ah[6], ah[7], bb.z, bb.w);
                }
                #pragma unroll
                for (int dq = 0; dq < 4; dq++) {
                    int ci = jt * 4 + dq;
                    float c = sigf(G[1][dq]) * c_st[ci] + sigf(G[0][dq]) * tanha(G[2][dq]);
                    c_st[ci] = c;
                    h_d[ci] = sigf(G[3][dq]) * tanha(c);
                }
            }
        }

        // ---- reduce 16 paths -> per-b sum, write ----
        #pragma unroll
        for (int jt = 0; jt < 4; jt++) {
            #pragma unroll
            for (int cc = 0; cc < 2; cc++) {
                float v = h_d[jt * 4 + cc] + h_d[jt * 4 + 2 + cc];
                v += __shfl_xor_sync(FULL, v, 4);
                v += __shfl_xor_sync(FULL, v, 8);
                v += __shfl_xor_sync(FULL, v, 16);
                if (lane < 4)
                    gout[b * 32 + 8 * jt + 2 * lane + cc] = v;
            }
        }
    }
}

// ---------------- combine: agg matmuls, scores, sigmoid, block loss partials ----------------
__global__ __launch_bounds__(256) void combine_kernel(
        const float* __restrict__ user_table,
        const float* __restrict__ ent_table,
        const float* __restrict__ agg_w,
        const float* __restrict__ agg_b,
        const int* __restrict__ users,
        const int* __restrict__ items,
        const int* __restrict__ ratings,
        float* __restrict__ out, int B) {
    __shared__ float aggT[32 * 32];
    __shared__ float aggb_sm[32];
    __shared__ float lred[8];
    int tid = threadIdx.x;
    for (int i = tid; i < 32 * 32; i += 256) {
        int k = i >> 5, j = i & 31;
        aggT[i] = agg_w[j * 32 + k];
    }
    if (tid < 32) aggb_sm[tid] = agg_b[tid];
    __syncthreads();

    int wid = tid >> 5, lane = tid & 31;
    int gw = blockIdx.x * 8 + wid, TW = gridDim.x * 8;
    float loss_acc = 0.f;

    for (int b = gw; b < B; b += TW) {
        int item = items[b];
        int user = users[b];

        float f0 = g_final0[b * 32 + lane];
        float f1 = g_final1[b * 32 + lane];

        float v = ent_table[item * 32 + lane] + f0;
        float acc = aggb_sm[lane];
        #pragma unroll
        for (int k = 0; k < 32; k++)
            acc += __shfl_sync(FULL, v, k) * aggT[k * 32 + lane];

        v = acc + f1;
        acc = aggb_sm[lane];
        #pragma unroll
        for (int k = 0; k < 32; k++)
            acc += __shfl_sync(FULL, v, k) * aggT[k * 32 + lane];

        float prod = user_table[user * 32 + lane] * acc;
        #pragma unroll
        for (int o = 16; o; o >>= 1) prod += __shfl_xor_sync(FULL, prod, o);

        if (lane == 0) {
            float s = prod;
            out[1 + b]     = 1.0f / (1.0f + __expf(-s));
            out[1 + B + b] = (float)item;
            float r    = (float)ratings[b];
            float ls_p = fminf(s, 0.0f)  - log1pf(__expf(-fabsf(s)));
            float ls_n = fminf(-s, 0.0f) - log1pf(__expf(-fabsf(s)));
            loss_acc += -(r * ls_p + (1.0f - r) * ls_n);
        }
    }

    if (lane == 0) lred[wid] = loss_acc;
    __syncthreads();
    if (tid == 0) {
        float s = 0.f;
        #pragma unroll
        for (int w = 0; w < 8; w++) s += lred[w];
        g_lossblk[blockIdx.x] = s;
    }
}

// ---------------- final loss reduction ----------------
__global__ void loss_kernel(float* __restrict__ out, int B, int nblk) {
    __shared__ float sm[512];
    int tid = threadIdx.x;
    float s = 0.f;
    for (int i = tid; i < nblk; i += 512) s += g_lossblk[i];
    sm[tid] = s;
    __syncthreads();
    for (int o = 256; o; o >>= 1) {
        if (tid < o) sm[tid] += sm[tid + o];
        __syncthreads();
    }
    if (tid == 0) out[0] = sm[0] / (float)B;
}

// ---------------- launch ----------------
extern "C" void kernel_launch(void* const* d_in, const int* in_sizes, int n_in,
                              void* d_out, int out_size) {
    const float* user_table = (const float*)d_in[0];
    const float* ent_table  = (const float*)d_in[1];
    const float* rel_table  = (const float*)d_in[2];
    const float* w_ih0      = (const float*)d_in[3];
    const float* w_hh0      = (const float*)d_in[4];
    const float* b_ih0      = (const float*)d_in[5];
    const float* b_hh0      = (const float*)d_in[6];
    const float* w_ih1      = (const float*)d_in[7];
    const float* w_hh1      = (const float*)d_in[8];
    const float* b_ih1      = (const float*)d_in[9];
    const float* b_hh1      = (const float*)d_in[10];
    const float* agg_w      = (const float*)d_in[11];
    const float* agg_b      = (const float*)d_in[12];
    const int*   users      = (const int*)d_in[13];
    const int*   items      = (const int*)d_in[14];
    const int*   ratings    = (const int*)d_in[15];
    const int*   lp0        = (const int*)d_in[16];
    const int*   lp1        = (const int*)d_in[17];
    float*       out        = (float*)d_out;

    int B = in_sizes[13];

    precompute_tables_kernel<<<4, 1024>>>(rel_table, ent_table, w_ih0, w_ih1,
                                          b_ih0, b_hh0, b_ih1, b_hh1);
    precompute_rt_kernel<<<dim3(128, 2), 256>>>();
    hop_mma_kernel<2, 3, 0><<<NBLK, 256>>>(w_hh0, w_ih0, user_table, users,
                                           items, lp0, B);
    hop_mma_kernel<3, 5, 1><<<NBLK, 256>>>(w_hh1, w_ih1, user_table, users,
                                           items, lp1, B);
    combine_kernel<<<NBLK, 256>>>(user_table, ent_table, agg_w, agg_b,
                                  users, items, ratings, out, B);
    loss_kernel<<<1, 512>>>(out, B, NBLK);
}